// round 6
// baseline (speedup 1.0000x reference)
#include <cuda_runtime.h>
#include <cstdint>

#define NN 8192
#define FF 8
#define NB 256                       // blocks (exact: 256*32 = 8192 rows)
#define GW 8                         // gemv warps per block
#define FWARPS 2                     // fid warps per block
#define TPB ((GW + FWARPS) * 32)     // 320
#define GT (GW * 32)                 // 256 gemv threads
#define GRPW 4                       // rows per gemv warp
#define RPB (GW * GRPW)              // 32 rows per block
#define CH 128                       // A columns per chunk/stage
#define NCH (NN / CH)                // 64 chunks
#define DEPTH 4                      // cp.async pipeline stages
#define STG (RPB * CH * 4)           // 16384 B per stage
#define XT 1024                      // x tile (nodes)
#define XBYTES (XT * 32)             // 32768
#define FTS 128                      // fid tile size
#define FT (NN / FTS)                // 64
#define NPAIRS (FT * (FT + 1) / 2)   // 2080
#define NFW (NB * FWARPS)            // 512 fid warps
#define RT9 0.94868329805051381f     // sqrt(0.9)

// shared memory layout (dynamic)
#define SM_A 0
#define SM_X (DEPTH * STG)                 // 65536
#define SM_PB (SM_X + XBYTES)              // 98304
#define SM_TOTAL (SM_PB + FWARPS * 4096)   // 106496

typedef unsigned long long ull;

__device__ float g_dense[NN * FF];   // accumulated message passing (zeroed per launch)

// ---------------- f32x2 helpers ----------------
__device__ __forceinline__ ull fma2(ull a, ull b, ull c) {
    ull d; asm("fma.rn.f32x2 %0, %1, %2, %3;" : "=l"(d) : "l"(a), "l"(b), "l"(c)); return d;
}
__device__ __forceinline__ ull mul2(ull a, ull b) {
    ull d; asm("mul.rn.f32x2 %0, %1, %2;" : "=l"(d) : "l"(a), "l"(b)); return d;
}
__device__ __forceinline__ ull add2(ull a, ull b) {
    ull d; asm("add.rn.f32x2 %0, %1, %2;" : "=l"(d) : "l"(a), "l"(b)); return d;
}
__device__ __forceinline__ ull pack2(float lo, float hi) {
    ull d; asm("mov.b64 %0, {%1, %2};" : "=l"(d) : "f"(lo), "f"(hi)); return d;
}
__device__ __forceinline__ void unpack2(ull v, float& lo, float& hi) {
    asm("mov.b64 {%0, %1}, %2;" : "=f"(lo), "=f"(hi) : "l"(v));
}
__device__ __forceinline__ float ftanh(float x) {
    float t = fabsf(x);
    float e = __expf(-2.0f * t);
    float r = __fdividef(1.0f - e, 1.0f + e);
    return copysignf(r, x);
}
__device__ __forceinline__ float fsigmoid(float x) {
    float e = __expf(-fabsf(x));
    float p = __fdividef(1.0f, 1.0f + e);
    return (x >= 0.0f) ? p : 1.0f - p;
}

// =================================================================
// Megakernel: warps 0-7 stream A via cp.async and accumulate A@X;
// warps 8-9 do the sparse fidelity corrections concurrently.
// Both sides atomicAdd into g_dense (memset-zeroed before launch).
// =================================================================
__global__ void __launch_bounds__(TPB, 2)
mega_kernel(const float* __restrict__ A, const float* __restrict__ X)
{
    extern __shared__ __align__(16) char sm[];
    const int tid  = threadIdx.x;
    const int lane = tid & 31;
    const int warp = tid >> 5;
    const int bid  = blockIdx.x;

    uint32_t smb;
    asm("{ .reg .u64 t; cvta.to.shared.u64 t, %1; cvt.u32.u64 %0, t; }"
        : "=r"(smb) : "l"(sm));

    if (warp < GW) {
        // ================= gemv side =================
        const int i0   = bid * RPB;
        const int wrow = warp * GRPW;

        // issue stage for chunk c into slot c%DEPTH (all 256 gemv threads)
        #define ISSUE(c)                                                        \
            do {                                                                \
                const int c_ = (c);                                             \
                const uint32_t dstb_ = smb + SM_A + (uint32_t)(c_ & (DEPTH-1)) * STG; \
                _Pragma("unroll")                                               \
                for (int p_ = 0; p_ < 4; p_++) {                                \
                    const int off_ = p_ * 4096 + tid * 16;                      \
                    const int row_ = off_ >> 9;                                 \
                    const float* g_ = A + (size_t)(i0 + row_) * NN              \
                                        + c_ * CH + ((off_ & 511) >> 2);        \
                    asm volatile("cp.async.cg.shared.global [%0], [%1], 16;"    \
                                 :: "r"(dstb_ + (uint32_t)off_), "l"(g_));      \
                }                                                               \
                asm volatile("cp.async.commit_group;" ::: "memory");            \
            } while (0)

        ull acc[GRPW][4];
        #pragma unroll
        for (int r = 0; r < GRPW; r++)
            #pragma unroll
            for (int kk = 0; kk < 4; kk++) acc[r][kk] = 0ull;

        // prologue: stages 0..DEPTH-2
        ISSUE(0); ISSUE(1); ISSUE(2);

        #define HALF(B, c0, c1, q0off)                                          \
            do {                                                                \
                ull pa0_, pa1_, pb0_, pb1_, pc0_, pc1_, pd0_, pd1_;             \
                asm("ld.shared.v2.b64 {%0, %1}, [%2];" : "=l"(pa0_), "=l"(pa1_) \
                    : "r"(ba_ + (q0off)));                                      \
                asm("ld.shared.v2.b64 {%0, %1}, [%2];" : "=l"(pb0_), "=l"(pb1_) \
                    : "r"(ba_ + (q0off) + 512));                                \
                asm("ld.shared.v2.b64 {%0, %1}, [%2];" : "=l"(pc0_), "=l"(pc1_) \
                    : "r"(ba_ + (q0off) + 1024));                               \
                asm("ld.shared.v2.b64 {%0, %1}, [%2];" : "=l"(pd0_), "=l"(pd1_) \
                    : "r"(ba_ + (q0off) + 1536));                               \
                _Pragma("unroll")                                               \
                for (int r_ = 0; r_ < GRPW; r_++) {                             \
                    ull w0_ = pack2((B)[r_].c0, (B)[r_].c0);                    \
                    acc[r_][0] = fma2(w0_, pa0_, acc[r_][0]);                   \
                    acc[r_][1] = fma2(w0_, pa1_, acc[r_][1]);                   \
                    acc[r_][2] = fma2(w0_, pb0_, acc[r_][2]);                   \
                    acc[r_][3] = fma2(w0_, pb1_, acc[r_][3]);                   \
                    ull w1_ = pack2((B)[r_].c1, (B)[r_].c1);                    \
                    acc[r_][0] = fma2(w1_, pc0_, acc[r_][0]);                   \
                    acc[r_][1] = fma2(w1_, pc1_, acc[r_][1]);                   \
                    acc[r_][2] = fma2(w1_, pd0_, acc[r_][2]);                   \
                    acc[r_][3] = fma2(w1_, pd1_, acc[r_][3]);                   \
                }                                                               \
            } while (0)

        #pragma unroll 1
        for (int n = 0; n < NCH; n++) {
            if ((n & 7) == 0) {
                // reload x tile (previous reads finished at prior end barrier)
                const int t0 = (n >> 3) * XT;
                for (int j = tid; j < XT; j += GT) {
                    const float4* xp = reinterpret_cast<const float4*>(X + (size_t)(t0 + j) * FF);
                    float4 a = __ldg(xp), b = __ldg(xp + 1);
                    const int cc = j >> 7, ll = (j >> 2) & 31, rr = j & 3;
                    ull* dst = reinterpret_cast<ull*>(sm + SM_X + cc * 4096 + (2 * rr) * 512 + ll * 16);
                    dst[0]  = pack2(a.x, a.y);
                    dst[1]  = pack2(a.z, a.w);
                    dst[64] = pack2(b.x, b.y);
                    dst[65] = pack2(b.z, b.w);
                }
            }
            asm volatile("cp.async.wait_group %0;" :: "n"(DEPTH - 2) : "memory");
            asm volatile("bar.sync 1, %0;" :: "n"(GT) : "memory");   // stage + x visible

            // compute chunk n
            {
                const uint32_t abase = smb + SM_A + (uint32_t)(n & (DEPTH-1)) * STG
                                     + (uint32_t)wrow * 512 + (uint32_t)lane * 16;
                float4 av[GRPW];
                #pragma unroll
                for (int r = 0; r < GRPW; r++)
                    asm("ld.shared.v4.b32 {%0, %1, %2, %3}, [%4];"
                        : "=f"(av[r].x), "=f"(av[r].y), "=f"(av[r].z), "=f"(av[r].w)
                        : "r"(abase + (uint32_t)r * 512));

                const uint32_t ba_ = smb + SM_X + (uint32_t)(n & 7) * 4096 + (uint32_t)lane * 16;
                HALF(av, x, y, 0);
                HALF(av, z, w, 2048);
            }

            asm volatile("bar.sync 1, %0;" :: "n"(GT) : "memory");   // all reads of slot done
            if (n + DEPTH - 1 < NCH) ISSUE(n + DEPTH - 1);
        }
        #undef ISSUE
        #undef HALF

        // warp butterfly reduction
        #pragma unroll
        for (int r = 0; r < GRPW; r++)
            #pragma unroll
            for (int kk = 0; kk < 4; kk++) {
                ull v = acc[r][kk];
                #pragma unroll
                for (int o = 16; o; o >>= 1)
                    v = add2(v, __shfl_xor_sync(0xffffffffu, v, o));
                acc[r][kk] = v;
            }

        if (lane < GRPW) {
            const int row = i0 + wrow + lane;
            #pragma unroll
            for (int kk = 0; kk < 4; kk++) {
                float lo, hi;
                unpack2(acc[lane][kk], lo, hi);
                atomicAdd(&g_dense[(size_t)row * FF + 2 * kk],     lo);
                atomicAdd(&g_dense[(size_t)row * FF + 2 * kk + 1], hi);
            }
        }
    } else {
        // ================= fid side =================
        // fid ⟺ |xn_i · xn_j| >= sqrt(0.9); hit makes weight exactly 1:
        // add (1-A)*x both directions.
        const int fw = bid * FWARPS + (warp - GW);
        ull* pb = reinterpret_cast<ull*>(sm + SM_PB + (warp - GW) * 4096);
        const uint32_t pbb = smb + SM_PB + (uint32_t)(warp - GW) * 4096;

        for (int p = fw; p < NPAIRS; p += NFW) {
            int ti = 0, rem = p;
            while (rem >= FT - ti) { rem -= FT - ti; ti++; }
            const int tj = ti + rem;

            __syncwarp();   // previous pair's pb reads done
            // stage normalized x of tile tj (lane handles 4 rows)
            #pragma unroll
            for (int k = 0; k < 4; k++) {
                const int row = lane + 32 * k;
                const float4* xp = reinterpret_cast<const float4*>(X + (size_t)(tj * FTS + row) * FF);
                float4 a = __ldg(xp), c = __ldg(xp + 1);
                float ss = a.x*a.x + a.y*a.y + a.z*a.z + a.w*a.w
                         + c.x*c.x + c.y*c.y + c.z*c.z + c.w*c.w;
                float inv = 1.0f / (sqrtf(ss) + 1e-12f);
                pb[row*4 + 0] = pack2(a.x*inv, a.y*inv);
                pb[row*4 + 1] = pack2(a.z*inv, a.w*inv);
                pb[row*4 + 2] = pack2(c.x*inv, c.y*inv);
                pb[row*4 + 3] = pack2(c.z*inv, c.w*inv);
            }
            // own 4 i-rows (tile ti) normalized into registers
            ull xi[4][4];
            #pragma unroll
            for (int k = 0; k < 4; k++) {
                const int row = lane + 32 * k;
                const float4* xp = reinterpret_cast<const float4*>(X + (size_t)(ti * FTS + row) * FF);
                float4 a = __ldg(xp), c = __ldg(xp + 1);
                float ss = a.x*a.x + a.y*a.y + a.z*a.z + a.w*a.w
                         + c.x*c.x + c.y*c.y + c.z*c.z + c.w*c.w;
                float inv = 1.0f / (sqrtf(ss) + 1e-12f);
                xi[k][0] = pack2(a.x*inv, a.y*inv);
                xi[k][1] = pack2(a.z*inv, a.w*inv);
                xi[k][2] = pack2(c.x*inv, c.y*inv);
                xi[k][3] = pack2(c.z*inv, c.w*inv);
            }
            __syncwarp();

            #pragma unroll 2
            for (int j = 0; j < FTS; j++) {
                ull q0, q1, q2, q3;
                asm("ld.shared.v2.b64 {%0, %1}, [%2];" : "=l"(q0), "=l"(q1)
                    : "r"(pbb + (uint32_t)j * 32));
                asm("ld.shared.v2.b64 {%0, %1}, [%2];" : "=l"(q2), "=l"(q3)
                    : "r"(pbb + (uint32_t)j * 32 + 16));
                #pragma unroll
                for (int k = 0; k < 4; k++) {
                    ull d = mul2(xi[k][0], q0);
                    d = fma2(xi[k][1], q1, d);
                    d = fma2(xi[k][2], q2, d);
                    d = fma2(xi[k][3], q3, d);
                    float lo, hi; unpack2(d, lo, hi);
                    const float s = lo + hi;
                    if (fabsf(s) >= RT9) {      // rare (~1e-4)
                        const int gi = ti * FTS + lane + 32 * k;
                        const int gj = tj * FTS + j;
                        if (ti != tj || gj > gi) {
                            const float aij = __ldg(A + (size_t)gi * NN + gj);
                            const float aji = __ldg(A + (size_t)gj * NN + gi);
                            const float* xjv = X + (size_t)gj * FF;
                            const float* xiv = X + (size_t)gi * FF;
                            #pragma unroll
                            for (int f = 0; f < FF; f++)
                                atomicAdd(&g_dense[(size_t)gi * FF + f], (1.0f - aij) * __ldg(xjv + f));
                            #pragma unroll
                            for (int f = 0; f < FF; f++)
                                atomicAdd(&g_dense[(size_t)gj * FF + f], (1.0f - aji) * __ldg(xiv + f));
                        }
                    }
                }
            }
        }
    }
}

// =================================================================
// MLP tail (weights staged in smem)
// =================================================================
#define NW_TOT 785
__global__ void __launch_bounds__(64)
mlp_kernel(const float* __restrict__ Wfm, const float* __restrict__ bfm,
           const float* __restrict__ Wc1, const float* __restrict__ bc1,
           const float* __restrict__ Wp1, const float* __restrict__ bp1,
           const float* __restrict__ Wc2, const float* __restrict__ bc2,
           const float* __restrict__ Wp2, const float* __restrict__ bp2,
           const float* __restrict__ Wc3, const float* __restrict__ bc3,
           const float* __restrict__ Wh,  const float* __restrict__ bh,
           float* __restrict__ out)
{
    __shared__ float w[NW_TOT];
    const int tid = threadIdx.x;

    struct Seg { const float* src; int off, n; };
    const Seg segs[14] = {
        {Wfm,   0, 128}, {bfm, 128, 16}, {Wc1, 144, 256}, {bc1, 400, 16},
        {Wp1, 416, 192}, {bp1, 608, 12}, {Wc2, 620,  96}, {bc2, 716,  8},
        {Wp2, 724,  32}, {bp2, 756,  4}, {Wc3, 760,  16}, {bc3, 776,  4},
        {Wh,  780,   4}, {bh,  784,  1}
    };
    #pragma unroll
    for (int s = 0; s < 14; s++)
        for (int k = tid; k < segs[s].n; k += 64)
            w[segs[s].off + k] = __ldg(segs[s].src + k);
    __syncthreads();

    const int i = blockIdx.x * 64 + tid;

    float v[16], h[16];
    #pragma unroll
    for (int k = 0; k < 8; k++) v[k] = g_dense[(size_t)i * FF + k];

    #define LAYER(IN, OUT, WOFF, BOFF, src, dst)                          \
        do {                                                              \
            _Pragma("unroll")                                             \
            for (int j_ = 0; j_ < (OUT); j_++) {                          \
                float s_ = w[(BOFF) + j_];                                \
                _Pragma("unroll")                                         \
                for (int k_ = 0; k_ < (IN); k_++)                         \
                    s_ = fmaf((src)[k_], w[(WOFF) + k_ * (OUT) + j_], s_);\
                (dst)[j_] = ftanh(s_);                                    \
            }                                                             \
        } while (0)

    LAYER(8, 16,   0, 128, v, h);
    LAYER(16, 16, 144, 400, h, v);
    LAYER(16, 12, 416, 608, v, h);
    LAYER(12, 8,  620, 716, h, v);
    LAYER(8, 4,   724, 756, v, h);
    LAYER(4, 4,   760, 776, h, v);
    #undef LAYER

    float z = w[784];
    #pragma unroll
    for (int k = 0; k < 4; k++)
        z = fmaf(v[k], w[780 + k], z);
    out[i] = fsigmoid(z);
}

extern "C" void kernel_launch(void* const* d_in, const int* in_sizes, int n_in,
                              void* d_out, int out_size)
{
    const float* A = (const float*)d_in[0];
    const float* X = (const float*)d_in[1];

    cudaFuncSetAttribute(mega_kernel,
                         cudaFuncAttributeMaxDynamicSharedMemorySize, SM_TOTAL);

    void* gd = nullptr;
    cudaGetSymbolAddress(&gd, g_dense);
    cudaMemsetAsync(gd, 0, sizeof(float) * NN * FF, 0);

    mega_kernel<<<NB, TPB, SM_TOTAL>>>(A, X);

    mlp_kernel<<<NN / 64, 64>>>(
        (const float*)d_in[2],  (const float*)d_in[3],
        (const float*)d_in[4],  (const float*)d_in[5],
        (const float*)d_in[6],  (const float*)d_in[7],
        (const float*)d_in[8],  (const float*)d_in[9],
        (const float*)d_in[10], (const float*)d_in[11],
        (const float*)d_in[12], (const float*)d_in[13],
        (const float*)d_in[14], (const float*)d_in[15],
        (float*)d_out);
}

// round 7
// speedup vs baseline: 1.2924x; 1.2924x over previous
#include <cuda_runtime.h>
#include <cstdint>

#define NN 8192
#define FF 8
#define TPB 128                      // 4 warps
#define GRPW 8                       // rows per warp
#define RPB 32                       // rows per gemv block
#define NGB (NN / RPB)               // 256 gemv blocks
#define CH 128                       // j per chunk (lane owns 4 consecutive j)
#define NCH (NN / CH)                // 64 chunks
#define XT 1024                      // x tile nodes (8 chunks)
#define FTS 128                      // fid tile
#define FT (NN / FTS)                // 64
#define NPAIRS (FT * (FT + 1) / 2)   // 2080 fid blocks (1 pair each)
#define GRID (NGB + NPAIRS)          // 2336
#define RT9 0.94868329805051381f     // sqrt(0.9)
#define SMEM_DYN 32768

typedef unsigned long long ull;

__device__ float g_dense[NN * FF];

// ---------------- f32x2 helpers ----------------
__device__ __forceinline__ ull fma2(ull a, ull b, ull c) {
    ull d; asm("fma.rn.f32x2 %0, %1, %2, %3;" : "=l"(d) : "l"(a), "l"(b), "l"(c)); return d;
}
__device__ __forceinline__ ull mul2(ull a, ull b) {
    ull d; asm("mul.rn.f32x2 %0, %1, %2;" : "=l"(d) : "l"(a), "l"(b)); return d;
}
__device__ __forceinline__ ull add2(ull a, ull b) {
    ull d; asm("add.rn.f32x2 %0, %1, %2;" : "=l"(d) : "l"(a), "l"(b)); return d;
}
__device__ __forceinline__ ull pack2(float lo, float hi) {
    ull d; asm("mov.b64 %0, {%1, %2};" : "=l"(d) : "f"(lo), "f"(hi)); return d;
}
__device__ __forceinline__ void unpack2(ull v, float& lo, float& hi) {
    asm("mov.b64 {%0, %1}, %2;" : "=f"(lo), "=f"(hi) : "l"(v));
}
__device__ __forceinline__ float ftanh(float x) {
    float t = fabsf(x);
    float e = __expf(-2.0f * t);
    float r = __fdividef(1.0f - e, 1.0f + e);
    return copysignf(r, x);
}
__device__ __forceinline__ float fsigmoid(float x) {
    float e = __expf(-fabsf(x));
    float p = __fdividef(1.0f, 1.0f + e);
    return (x >= 0.0f) ? p : 1.0f - p;
}

// =================================================================
// Mixed kernel: blocks [0,256) do the dense gemv (A @ X), blocks
// [256, 2336) each handle one fid tile-pair. Both atomicAdd into
// g_dense (zeroed before launch). fid blocks are issue-bound and
// overlap with the DRAM-bound gemv blocks on the same SMs.
// =================================================================
__global__ void __launch_bounds__(TPB, 3)
mixed_kernel(const float* __restrict__ A, const float* __restrict__ X)
{
    extern __shared__ __align__(16) char sm[];
    const int tid  = threadIdx.x;
    const int lane = tid & 31;
    const int warp = tid >> 5;

    uint32_t smb;
    asm("{ .reg .u64 t; cvta.to.shared.u64 t, %1; cvt.u32.u64 %0, t; }"
        : "=r"(smb) : "l"(sm));

    if (blockIdx.x < NGB) {
        // ===================== gemv =====================
        // smem x layout (position-permuted): node j in tile:
        // c=j>>7 (chunk), l=(j>>2)&31 (lane), r=j&3; features (2k,2k+1)
        // pairs live at c*4096 + (2r+{0,1})*512 + l*16 (+64B for f4-7)
        const int i0 = blockIdx.x * RPB + warp * GRPW;

        ull acc[GRPW][4];
        #pragma unroll
        for (int r = 0; r < GRPW; r++)
            #pragma unroll
            for (int kk = 0; kk < 4; kk++) acc[r][kk] = 0ull;

        const float* Ab = A + (size_t)i0 * NN + lane * 4;
        float4 b0[GRPW], b1[GRPW];

        #define LDA(n, B)                                                      \
            do {                                                               \
                int n_ = (n); if (n_ >= NCH) n_ -= NCH;                        \
                const float* p_ = Ab + (size_t)n_ * CH;                        \
                _Pragma("unroll")                                              \
                for (int r_ = 0; r_ < GRPW; r_++)                              \
                    (B)[r_] = __ldcs(reinterpret_cast<const float4*>(p_ + (size_t)r_ * NN)); \
            } while (0)

        #define HALF(B, c0, c1, q0off)                                         \
            do {                                                                \
                ull pa0_, pa1_, pb0_, pb1_, pc0_, pc1_, pd0_, pd1_;             \
                asm("ld.shared.v2.b64 {%0, %1}, [%2];" : "=l"(pa0_), "=l"(pa1_) \
                    : "r"(ba_ + (q0off)));                                      \
                asm("ld.shared.v2.b64 {%0, %1}, [%2];" : "=l"(pb0_), "=l"(pb1_) \
                    : "r"(ba_ + (q0off) + 512));                                \
                asm("ld.shared.v2.b64 {%0, %1}, [%2];" : "=l"(pc0_), "=l"(pc1_) \
                    : "r"(ba_ + (q0off) + 1024));                               \
                asm("ld.shared.v2.b64 {%0, %1}, [%2];" : "=l"(pd0_), "=l"(pd1_) \
                    : "r"(ba_ + (q0off) + 1536));                               \
                _Pragma("unroll")                                               \
                for (int r_ = 0; r_ < GRPW; r_++) {                             \
                    ull w0_ = pack2((B)[r_].c0, (B)[r_].c0);                    \
                    acc[r_][0] = fma2(w0_, pa0_, acc[r_][0]);                   \
                    acc[r_][1] = fma2(w0_, pa1_, acc[r_][1]);                   \
                    acc[r_][2] = fma2(w0_, pb0_, acc[r_][2]);                   \
                    acc[r_][3] = fma2(w0_, pb1_, acc[r_][3]);                   \
                    ull w1_ = pack2((B)[r_].c1, (B)[r_].c1);                    \
                    acc[r_][0] = fma2(w1_, pc0_, acc[r_][0]);                   \
                    acc[r_][1] = fma2(w1_, pc1_, acc[r_][1]);                   \
                    acc[r_][2] = fma2(w1_, pd0_, acc[r_][2]);                   \
                    acc[r_][3] = fma2(w1_, pd1_, acc[r_][3]);                   \
                }                                                               \
            } while (0)

        #define COMPUTE(cl, B)                                                  \
            do {                                                                \
                const uint32_t ba_ = smb + (uint32_t)(cl) * 4096 + (uint32_t)lane * 16; \
                HALF(B, x, y, 0);                                               \
                HALF(B, z, w, 2048);                                            \
            } while (0)

        LDA(0, b0); LDA(1, b1);

        #pragma unroll 1
        for (int t = 0; t < NCH / 8; t++) {
            __syncthreads();     // previous tile fully consumed
            const int t0 = t * XT;
            for (int j = tid; j < XT; j += TPB) {
                const float4* xp = reinterpret_cast<const float4*>(X + (size_t)(t0 + j) * FF);
                float4 a = __ldg(xp), b = __ldg(xp + 1);
                const int cc = j >> 7, ll = (j >> 2) & 31, rr = j & 3;
                ull* dst = reinterpret_cast<ull*>(sm + cc * 4096 + (2 * rr) * 512 + ll * 16);
                dst[0]  = pack2(a.x, a.y);
                dst[1]  = pack2(a.z, a.w);
                dst[64] = pack2(b.x, b.y);
                dst[65] = pack2(b.z, b.w);
            }
            __syncthreads();

            #pragma unroll 1
            for (int cc = 0; cc < 8; cc += 2) {
                const int n = t * 8 + cc;
                COMPUTE(cc,     b0); LDA(n + 2, b0);
                COMPUTE(cc + 1, b1); LDA(n + 3, b1);
            }
        }
        #undef LDA
        #undef HALF
        #undef COMPUTE

        // warp butterfly reduction
        #pragma unroll
        for (int r = 0; r < GRPW; r++)
            #pragma unroll
            for (int kk = 0; kk < 4; kk++) {
                ull v = acc[r][kk];
                #pragma unroll
                for (int o = 16; o; o >>= 1)
                    v = add2(v, __shfl_xor_sync(0xffffffffu, v, o));
                acc[r][kk] = v;
            }

        if (lane < GRPW) {
            const int row = i0 + lane;
            #pragma unroll
            for (int kk = 0; kk < 4; kk++) {
                float lo, hi;
                unpack2(acc[lane][kk], lo, hi);
                atomicAdd(&g_dense[(size_t)row * FF + 2 * kk],     lo);
                atomicAdd(&g_dense[(size_t)row * FF + 2 * kk + 1], hi);
            }
        }
    } else {
        // ===================== fid =====================
        // one tile-pair per block; fid ⟺ |xn_i·xn_j| >= sqrt(0.9);
        // hit makes the effective weight exactly 1: add (1-A)*x.
        int p = blockIdx.x - NGB, ti = 0, rem = p;
        while (rem >= FT - ti) { rem -= FT - ti; ti++; }
        const int tj = ti + rem;

        ull* pb = reinterpret_cast<ull*>(sm);
        const uint32_t pbb = smb;
        const int t = tid;

        // own i-row normalized (registers)
        ull xi0, xi1, xi2, xi3;
        {
            const float4* xp = reinterpret_cast<const float4*>(X + (size_t)(ti * FTS + t) * FF);
            float4 a = __ldg(xp), c = __ldg(xp + 1);
            float ss = a.x*a.x + a.y*a.y + a.z*a.z + a.w*a.w
                     + c.x*c.x + c.y*c.y + c.z*c.z + c.w*c.w;
            float inv = 1.0f / (sqrtf(ss) + 1e-12f);
            xi0 = pack2(a.x*inv, a.y*inv);
            xi1 = pack2(a.z*inv, a.w*inv);
            xi2 = pack2(c.x*inv, c.y*inv);
            xi3 = pack2(c.z*inv, c.w*inv);
        }
        // j-tile normalized into smem (32B per node)
        {
            const float4* xp = reinterpret_cast<const float4*>(X + (size_t)(tj * FTS + t) * FF);
            float4 a = __ldg(xp), c = __ldg(xp + 1);
            float ss = a.x*a.x + a.y*a.y + a.z*a.z + a.w*a.w
                     + c.x*c.x + c.y*c.y + c.z*c.z + c.w*c.w;
            float inv = 1.0f / (sqrtf(ss) + 1e-12f);
            pb[t*4 + 0] = pack2(a.x*inv, a.y*inv);
            pb[t*4 + 1] = pack2(a.z*inv, a.w*inv);
            pb[t*4 + 2] = pack2(c.x*inv, c.y*inv);
            pb[t*4 + 3] = pack2(c.z*inv, c.w*inv);
        }
        __syncthreads();

        const int jstart = (ti == tj) ? (t + 1) : 0;

        #pragma unroll 4
        for (int j = jstart; j < FTS; j++) {
            ull q0, q1, q2, q3;
            asm("ld.shared.v2.b64 {%0, %1}, [%2];" : "=l"(q0), "=l"(q1)
                : "r"(pbb + (uint32_t)j * 32));
            asm("ld.shared.v2.b64 {%0, %1}, [%2];" : "=l"(q2), "=l"(q3)
                : "r"(pbb + (uint32_t)j * 32 + 16));
            ull d = mul2(xi0, q0);
            d = fma2(xi1, q1, d);
            d = fma2(xi2, q2, d);
            d = fma2(xi3, q3, d);
            float lo, hi; unpack2(d, lo, hi);
            const float s = lo + hi;
            if (fabsf(s) >= RT9) {           // rare (~1e-4)
                const int gi = ti * FTS + t;
                const int gj = tj * FTS + j;
                const float aij = __ldg(A + (size_t)gi * NN + gj);
                const float aji = __ldg(A + (size_t)gj * NN + gi);
                const float* xjv = X + (size_t)gj * FF;
                const float* xiv = X + (size_t)gi * FF;
                #pragma unroll
                for (int f = 0; f < FF; f++)
                    atomicAdd(&g_dense[(size_t)gi * FF + f], (1.0f - aij) * __ldg(xjv + f));
                #pragma unroll
                for (int f = 0; f < FF; f++)
                    atomicAdd(&g_dense[(size_t)gj * FF + f], (1.0f - aji) * __ldg(xiv + f));
            }
        }
    }
}

// =================================================================
// MLP tail (weights staged in smem), 256-thread blocks
// =================================================================
#define NW_TOT 785
__global__ void __launch_bounds__(256)
mlp_kernel(const float* __restrict__ Wfm, const float* __restrict__ bfm,
           const float* __restrict__ Wc1, const float* __restrict__ bc1,
           const float* __restrict__ Wp1, const float* __restrict__ bp1,
           const float* __restrict__ Wc2, const float* __restrict__ bc2,
           const float* __restrict__ Wp2, const float* __restrict__ bp2,
           const float* __restrict__ Wc3, const float* __restrict__ bc3,
           const float* __restrict__ Wh,  const float* __restrict__ bh,
           float* __restrict__ out)
{
    __shared__ float w[NW_TOT];
    const int tid = threadIdx.x;

    struct Seg { const float* src; int off, n; };
    const Seg segs[14] = {
        {Wfm,   0, 128}, {bfm, 128, 16}, {Wc1, 144, 256}, {bc1, 400, 16},
        {Wp1, 416, 192}, {bp1, 608, 12}, {Wc2, 620,  96}, {bc2, 716,  8},
        {Wp2, 724,  32}, {bp2, 756,  4}, {Wc3, 760,  16}, {bc3, 776,  4},
        {Wh,  780,   4}, {bh,  784,  1}
    };
    #pragma unroll
    for (int s = 0; s < 14; s++)
        for (int k = tid; k < segs[s].n; k += 256)
            w[segs[s].off + k] = __ldg(segs[s].src + k);
    __syncthreads();

    const int i = blockIdx.x * 256 + tid;

    float v[16], h[16];
    #pragma unroll
    for (int k = 0; k < 8; k++) v[k] = g_dense[(size_t)i * FF + k];

    #define LAYER(IN, OUT, WOFF, BOFF, src, dst)                          \
        do {                                                              \
            _Pragma("unroll")                                             \
            for (int j_ = 0; j_ < (OUT); j_++) {                          \
                float s_ = w[(BOFF) + j_];                                \
                _Pragma("unroll")                                         \
                for (int k_ = 0; k_ < (IN); k_++)                         \
                    s_ = fmaf((src)[k_], w[(WOFF) + k_ * (OUT) + j_], s_);\
                (dst)[j_] = ftanh(s_);                                    \
            }                                                             \
        } while (0)

    LAYER(8, 16,   0, 128, v, h);
    LAYER(16, 16, 144, 400, h, v);
    LAYER(16, 12, 416, 608, v, h);
    LAYER(12, 8,  620, 716, h, v);
    LAYER(8, 4,   724, 756, v, h);
    LAYER(4, 4,   760, 776, h, v);
    #undef LAYER

    float z = w[784];
    #pragma unroll
    for (int k = 0; k < 4; k++)
        z = fmaf(v[k], w[780 + k], z);
    out[i] = fsigmoid(z);
}

extern "C" void kernel_launch(void* const* d_in, const int* in_sizes, int n_in,
                              void* d_out, int out_size)
{
    const float* A = (const float*)d_in[0];
    const float* X = (const float*)d_in[1];

    void* gd = nullptr;
    cudaGetSymbolAddress(&gd, g_dense);
    cudaMemsetAsync(gd, 0, sizeof(float) * NN * FF, 0);

    mixed_kernel<<<GRID, TPB, SMEM_DYN>>>(A, X);

    mlp_kernel<<<NN / 256, 256>>>(
        (const float*)d_in[2],  (const float*)d_in[3],
        (const float*)d_in[4],  (const float*)d_in[5],
        (const float*)d_in[6],  (const float*)d_in[7],
        (const float*)d_in[8],  (const float*)d_in[9],
        (const float*)d_in[10], (const float*)d_in[11],
        (const float*)d_in[12], (const float*)d_in[13],
        (const float*)d_in[14], (const float*)d_in[15],
        (float*)d_out);
}